// round 14
// baseline (speedup 1.0000x reference)
#include <cuda_runtime.h>
#include <math.h>

#define IMG_W 1024
#define IMG_H 1024
#define BATCH 8
#define CH    3
#define NPIX  (IMG_H * IMG_W)

// Scratch (static device globals — no allocation allowed)
// Transposed magnitude: magT[pixel*8 + batch] — one 32B sector per pixel
__device__ float         g_magT[NPIX * BATCH];  // 32 MB
__device__ unsigned char g_idx [BATCH * NPIX];  //  8 MB

// Direction offsets for dirf[d]: position of the -1 tap (dy, dx)
__constant__ int c_dy[8] = {0, 1, 1, 1, 0, -1, -1, -1};
__constant__ int c_dx[8] = {1, 1, 0, -1, -1, -1, 0, 1};

#define TX 32
#define TY 16
#define IN_W 38
#define IN_H 22
#define HB_W 34
#define BL_H 18
#define IN_WP 40
#define HB_WP 36

// 5-tap gaussian, NEON-dot pattern (FROZEN NUMERICS — R12 passing variant)
__device__ __forceinline__ float gauss5(float x0, float x1, float x2, float x3, float x4) {
    const float G0 = 0.13533528323661270f;
    const float G1 = 0.60653065971263342f;
    float p0 = __fmul_rn(G0, x0);
    float p1 = __fmul_rn(G1, x1);
    float p2 = x2;
    float p3 = __fmul_rn(G1, x3);
    float p4 = __fmul_rn(G0, x4);
    return __fadd_rn(__fadd_rn(__fadd_rn(p0, p1), __fadd_rn(p2, p3)), p4);
}

// Fast atan2 approximation: octant reduction + Taylor-13 on [0, tan(pi/8)].
// |error| <= ~1e-6 rad. Zeros/NaN flagged 'bad' -> exact slow path.
__device__ __forceinline__ float fast_atan2(float y, float x, bool& bad) {
    float ax = fabsf(x), ay = fabsf(y);
    float mn = fminf(ax, ay), mx = fmaxf(ax, ay);
    bad |= !(mn > 0.0f);
    float t = __fdividef(mn, mx);
    bool red = (t > 0.414213562f);
    float u = red ? __fdividef(t - 1.0f, t + 1.0f) : t;
    float u2 = u * u;
    float c = fmaf(u2, 0.0769230769f, -0.0909090909f);   // 1/13, -1/11
    c = fmaf(u2, c, 0.1111111111f);                      //  1/9
    c = fmaf(u2, c, -0.1428571429f);                     // -1/7
    c = fmaf(u2, c, 0.2f);                               //  1/5
    c = fmaf(u2, c, -0.3333333333f);                     // -1/3
    float r = fmaf(u * u2, c, u);
    if (red) r = r + 0.78539816339744831f;
    if (ay > ax) r = 1.57079632679489662f - r;
    if (x < 0.0f) r = 3.14159265358979324f - r;
    return (y < 0.0f) ? -r : r;
}

__global__ __launch_bounds__(TX * TY) void k1_grad(const float* __restrict__ img) {
    __shared__ float s_in[CH][IN_H][IN_WP];
    __shared__ float s_h [CH][IN_H][HB_WP];
    __shared__ float s_b [CH][BL_H][HB_WP];

    const int b  = blockIdx.z;
    const int x0 = blockIdx.x * TX;
    const int y0 = blockIdx.y * TY;
    const int tx = threadIdx.x, ty = threadIdx.y;

    const bool interior = (x0 >= 3) & (x0 + IN_W - 3 <= IMG_W) &
                          (y0 >= 3) & (y0 + IN_H - 3 <= IMG_H);

    // ---- Phase 1: load 38x22 tiles for all 3 channels ----
    #pragma unroll
    for (int c = 0; c < CH; c++) {
        const float* ip = img + (size_t)(b * CH + c) * NPIX;
        if (interior) {
            const float* rp0 = ip + (y0 + ty - 3) * IMG_W + (x0 - 3);
            s_in[c][ty][tx] = __ldg(rp0 + tx);
            if (tx < IN_W - TX) s_in[c][ty][tx + TX] = __ldg(rp0 + tx + TX);
            if (ty < IN_H - TY) {
                const float* rp1 = rp0 + TY * IMG_W;
                s_in[c][ty + TY][tx] = __ldg(rp1 + tx);
                if (tx < IN_W - TX) s_in[c][ty + TY][tx + TX] = __ldg(rp1 + tx + TX);
            }
        } else {
            #pragma unroll
            for (int d2 = 0; d2 < 2; d2++) {
                int iy = ty + d2 * TY;
                if (iy < IN_H) {
                    int gy = y0 + iy - 3;
                    #pragma unroll
                    for (int d1 = 0; d1 < 2; d1++) {
                        int ix = tx + d1 * TX;
                        if (ix < IN_W) {
                            int gx = x0 + ix - 3;
                            float v = 0.0f;
                            if ((unsigned)gy < IMG_H && (unsigned)gx < IMG_W)
                                v = __ldg(ip + gy * IMG_W + gx);
                            s_in[c][iy][ix] = v;
                        }
                    }
                }
            }
        }
    }
    __syncthreads();

    // ---- Phase 2: horizontal blur ----
    #pragma unroll
    for (int c = 0; c < CH; c++) {
        {
            const float* r = s_in[c][ty];
            s_h[c][ty][tx] = gauss5(r[tx], r[tx+1], r[tx+2], r[tx+3], r[tx+4]);
            if (tx < HB_W - TX) {
                int hx = tx + TX;
                s_h[c][ty][hx] = gauss5(r[hx], r[hx+1], r[hx+2], r[hx+3], r[hx+4]);
            }
        }
        if (ty < IN_H - TY) {
            const float* r = s_in[c][ty + TY];
            s_h[c][ty+TY][tx] = gauss5(r[tx], r[tx+1], r[tx+2], r[tx+3], r[tx+4]);
            if (tx < HB_W - TX) {
                int hx = tx + TX;
                s_h[c][ty+TY][hx] = gauss5(r[hx], r[hx+1], r[hx+2], r[hx+3], r[hx+4]);
            }
        }
    }
    __syncthreads();

    // ---- Phase 3: vertical blur (masked outside image) ----
    #pragma unroll
    for (int c = 0; c < CH; c++) {
        #pragma unroll
        for (int d2 = 0; d2 < 2; d2++) {
            int by = ty + d2 * TY;
            if (by < BL_H) {
                #pragma unroll
                for (int d1 = 0; d1 < 2; d1++) {
                    int hx = tx + d1 * TX;
                    if (hx < HB_W) {
                        float v;
                        if (interior) {
                            v = gauss5(s_h[c][by][hx], s_h[c][by+1][hx], s_h[c][by+2][hx],
                                       s_h[c][by+3][hx], s_h[c][by+4][hx]);
                        } else {
                            int gy = y0 + by - 1, gx = x0 + hx - 1;
                            v = 0.0f;
                            if ((unsigned)gy < IMG_H && (unsigned)gx < IMG_W)
                                v = gauss5(s_h[c][by][hx], s_h[c][by+1][hx], s_h[c][by+2][hx],
                                           s_h[c][by+3][hx], s_h[c][by+4][hx]);
                        }
                        s_b[c][by][hx] = v;
                    }
                }
            }
        }
    }
    __syncthreads();

    // ---- Phase 4: Sobel (FROZEN) + mag; hybrid atan2 for bin index ----
    float magAcc = 0.0f, oriApp = 0.0f;
    float sgx[CH], sgy[CH];
    bool bad = false;
    #pragma unroll
    for (int c = 0; c < CH; c++) {
        float a00 = s_b[c][ty  ][tx], a01 = s_b[c][ty  ][tx+1], a02 = s_b[c][ty  ][tx+2];
        float a10 = s_b[c][ty+1][tx],                           a12 = s_b[c][ty+1][tx+2];
        float a20 = s_b[c][ty+2][tx], a21 = s_b[c][ty+2][tx+1], a22 = s_b[c][ty+2][tx+2];

        float gl0 = a00;
        float gl1 = __fmul_rn(-2.0f, a12);
        float gl2 = __fsub_rn(a20, a02);
        float gl3 = __fmul_rn(2.0f, a10);
        float gx  = __fadd_rn(__fadd_rn(__fadd_rn(gl0, gl1), __fadd_rn(gl2, gl3)),
                              __fmul_rn(-1.0f, a22));

        float hl0 = a00;
        float hl1 = __fmul_rn(2.0f, a01);
        float hl2 = __fsub_rn(a02, a20);
        float hl3 = __fmul_rn(-2.0f, a21);
        float gy  = __fadd_rn(__fadd_rn(__fadd_rn(hl0, hl1), __fadd_rn(hl2, hl3)),
                              __fmul_rn(-1.0f, a22));

        sgx[c] = gx; sgy[c] = gy;
        float sq = __fadd_rn(__fmul_rn(gx, gx), __fmul_rn(gy, gy));
        magAcc = __fadd_rn(magAcc, __fsqrt_rn(sq));
        oriApp = oriApp + fast_atan2(gy, gx, bad);
    }

    int y = y0 + ty, x = x0 + tx;
    int t = y * IMG_W + x;
    g_magT[t * BATCH + b] = magAcc;

    // approximate q; exact recompute only near bin boundaries (|dq|<=1e-5 << 1e-3)
    float q = __fdiv_rn(__fadd_rn(__fmul_rn(oriApp, 57.295779513082323f), 180.0f), 45.0f);
    float fr = q - floorf(q);
    bool safe = (!bad) && (fabsf(fr - 0.5f) > 1e-3f);
    if (!safe) {
        float s = 0.0f;
        #pragma unroll
        for (int c = 0; c < CH; c++)
            s = __fadd_rn(s, atan2f(sgy[c], sgx[c]));   // exact R12 chain
        q = __fdiv_rn(__fadd_rn(__fmul_rn(s, 57.295779513082323f), 180.0f), 45.0f);
    }
    int k = (int)rintf(q);
    g_idx[b * NPIX + t] = (unsigned char)(k & 7);
}

// ------------- Kernel 2+3 fused: NMS (transposed gathers) + hysteresis -----
__global__ __launch_bounds__(TX * TY) void k23(float* __restrict__ out) {
    __shared__ float s_t[BL_H][HB_WP];

    const int b  = blockIdx.z;
    const int x0 = blockIdx.x * TX;
    const int y0 = blockIdx.y * TY;
    const int tx = threadIdx.x, ty = threadIdx.y;
    const int base = b * NPIX;
    const int noff = c_dy[b] * IMG_W + c_dx[b];
    const int ddy = c_dy[b], ddx = c_dx[b];

    #pragma unroll
    for (int d2 = 0; d2 < 2; d2++) {
        int r = ty + d2 * TY;
        if (r < BL_H) {
            #pragma unroll
            for (int d1 = 0; d1 < 2; d1++) {
                int cc = tx + d1 * TX;
                if (cc < HB_W) {
                    int y = y0 + r - 1, x = x0 + cc - 1;
                    float tv = 0.0f;
                    if ((unsigned)y < IMG_H && (unsigned)x < IMG_W) {
                        int t  = y * IMG_W + x;
                        int d  = (int)__ldg(&g_idx[base + t]);
                        int dn = (d + 4) & 7;
                        const float* sec = &g_magT[t * BATCH];     // one 32B sector
                        float pos = __ldg(sec + d);
                        float neg = __ldg(sec + dn);
                        int ny = y + ddy, nx = x + ddx;
                        if ((unsigned)ny < IMG_H && (unsigned)nx < IMG_W) {
                            const float* nsec = &g_magT[(t + noff) * BATCH];
                            pos = __fsub_rn(pos, __ldg(nsec + d));
                            neg = __fsub_rn(neg, __ldg(nsec + dn));
                        }
                        if (fminf(pos, neg) > 0.0f) tv = __ldg(sec + b);
                    }
                    s_t[r][cc] = tv;
                }
            }
        }
    }
    __syncthreads();

    int y = y0 + ty, x = x0 + tx;
    float e = 0.0f;
    if (y > 0 && y < IMG_H - 1 && x > 0 && x < IMG_W - 1) {
        float tc = s_t[ty + 1][tx + 1];
        if (tc > 100.0f) {
            e = 1.0f;
        } else if (tc >= 10.0f) {
            bool any =
                (s_t[ty    ][tx] > 100.0f) | (s_t[ty    ][tx+1] > 100.0f) | (s_t[ty    ][tx+2] > 100.0f) |
                (s_t[ty + 1][tx] > 100.0f) |                               (s_t[ty + 1][tx+2] > 100.0f) |
                (s_t[ty + 2][tx] > 100.0f) | (s_t[ty + 2][tx+1] > 100.0f) | (s_t[ty + 2][tx+2] > 100.0f);
            e = any ? 1.0f : 0.0f;
        }
    }
    out[base + y * IMG_W + x] = e;
}

// ---------------- Launch ---------------------------------------------------
extern "C" void kernel_launch(void* const* d_in, const int* in_sizes, int n_in,
                              void* d_out, int out_size) {
    const float* img = (const float*)d_in[0];
    float* out = (float*)d_out;

    dim3 blk(TX, TY), grd(IMG_W / TX, IMG_H / TY, BATCH);
    k1_grad<<<grd, blk>>>(img);
    k23<<<grd, blk>>>(out);
}

// round 15
// speedup vs baseline: 1.6809x; 1.6809x over previous
#include <cuda_runtime.h>
#include <math.h>

#define IMG_W 1024
#define IMG_H 1024
#define BATCH 8
#define CH    3
#define NPIX  (IMG_H * IMG_W)

// Scratch (static device globals — no allocation allowed)
__device__ float         g_mag[BATCH * NPIX];   // 32 MB  [batch][pixel]
__device__ unsigned char g_idx[BATCH * NPIX];   //  8 MB
__device__ float         g_thin[BATCH * NPIX];  // 32 MB

// Direction offsets for dirf[d]: position of the -1 tap (dy, dx)
__constant__ int c_dy[8] = {0, 1, 1, 1, 0, -1, -1, -1};
__constant__ int c_dx[8] = {1, 1, 0, -1, -1, -1, 0, 1};

#define TX 32
#define TY 16
#define IN_W 38
#define IN_H 22
#define HB_W 34
#define BL_H 18
#define IN_WP 40
#define HB_WP 36

// 5-tap gaussian, NEON-dot pattern (FROZEN NUMERICS — R12 passing variant)
__device__ __forceinline__ float gauss5(float x0, float x1, float x2, float x3, float x4) {
    const float G0 = 0.13533528323661270f;
    const float G1 = 0.60653065971263342f;
    float p0 = __fmul_rn(G0, x0);
    float p1 = __fmul_rn(G1, x1);
    float p2 = x2;
    float p3 = __fmul_rn(G1, x3);
    float p4 = __fmul_rn(G0, x4);
    return __fadd_rn(__fadd_rn(__fadd_rn(p0, p1), __fadd_rn(p2, p3)), p4);
}

// Fast atan2: octant reduction + Taylor-13. |err| <= ~1e-6 rad.
// Zero/NaN operands flag 'bad' -> exact slow path.
__device__ __forceinline__ float fast_atan2(float y, float x, bool& bad) {
    float ax = fabsf(x), ay = fabsf(y);
    float mn = fminf(ax, ay), mx = fmaxf(ax, ay);
    bad |= !(mn > 0.0f);
    float t = __fdividef(mn, mx);
    bool red = (t > 0.414213562f);
    float u = red ? __fdividef(t - 1.0f, t + 1.0f) : t;
    float u2 = u * u;
    float c = fmaf(u2, 0.0769230769f, -0.0909090909f);
    c = fmaf(u2, c, 0.1111111111f);
    c = fmaf(u2, c, -0.1428571429f);
    c = fmaf(u2, c, 0.2f);
    c = fmaf(u2, c, -0.3333333333f);
    float r = fmaf(u * u2, c, u);
    if (red) r = r + 0.78539816339744831f;
    if (ay > ax) r = 1.57079632679489662f - r;
    if (x < 0.0f) r = 3.14159265358979324f - r;
    return (y < 0.0f) ? -r : r;
}

// Sobel from smem, FROZEN NEON-dot association (exact R12 ops)
__device__ __forceinline__ void sobel_frozen(const float (*sb)[HB_WP], int ty, int tx,
                                             float& gx, float& gy) {
    float a00 = sb[ty  ][tx], a01 = sb[ty  ][tx+1], a02 = sb[ty  ][tx+2];
    float a10 = sb[ty+1][tx],                       a12 = sb[ty+1][tx+2];
    float a20 = sb[ty+2][tx], a21 = sb[ty+2][tx+1], a22 = sb[ty+2][tx+2];

    float gl0 = a00;
    float gl1 = __fmul_rn(-2.0f, a12);
    float gl2 = __fsub_rn(a20, a02);
    float gl3 = __fmul_rn(2.0f, a10);
    gx = __fadd_rn(__fadd_rn(__fadd_rn(gl0, gl1), __fadd_rn(gl2, gl3)),
                   __fmul_rn(-1.0f, a22));

    float hl0 = a00;
    float hl1 = __fmul_rn(2.0f, a01);
    float hl2 = __fsub_rn(a02, a20);
    float hl3 = __fmul_rn(-2.0f, a21);
    gy = __fadd_rn(__fadd_rn(__fadd_rn(hl0, hl1), __fadd_rn(hl2, hl3)),
                   __fmul_rn(-1.0f, a22));
}

__global__ __launch_bounds__(TX * TY) void k1_grad(const float* __restrict__ img) {
    __shared__ float s_in[CH][IN_H][IN_WP];
    __shared__ float s_h [CH][IN_H][HB_WP];
    __shared__ float s_b [CH][BL_H][HB_WP];

    const int b  = blockIdx.z;
    const int x0 = blockIdx.x * TX;
    const int y0 = blockIdx.y * TY;
    const int tx = threadIdx.x, ty = threadIdx.y;

    const bool interior = (x0 >= 3) & (x0 + IN_W - 3 <= IMG_W) &
                          (y0 >= 3) & (y0 + IN_H - 3 <= IMG_H);

    // ---- Phase 1: load 38x22 tiles for all 3 channels ----
    #pragma unroll
    for (int c = 0; c < CH; c++) {
        const float* ip = img + (size_t)(b * CH + c) * NPIX;
        if (interior) {
            const float* rp0 = ip + (y0 + ty - 3) * IMG_W + (x0 - 3);
            s_in[c][ty][tx] = __ldg(rp0 + tx);
            if (tx < IN_W - TX) s_in[c][ty][tx + TX] = __ldg(rp0 + tx + TX);
            if (ty < IN_H - TY) {
                const float* rp1 = rp0 + TY * IMG_W;
                s_in[c][ty + TY][tx] = __ldg(rp1 + tx);
                if (tx < IN_W - TX) s_in[c][ty + TY][tx + TX] = __ldg(rp1 + tx + TX);
            }
        } else {
            #pragma unroll
            for (int d2 = 0; d2 < 2; d2++) {
                int iy = ty + d2 * TY;
                if (iy < IN_H) {
                    int gy = y0 + iy - 3;
                    #pragma unroll
                    for (int d1 = 0; d1 < 2; d1++) {
                        int ix = tx + d1 * TX;
                        if (ix < IN_W) {
                            int gxx = x0 + ix - 3;
                            float v = 0.0f;
                            if ((unsigned)gy < IMG_H && (unsigned)gxx < IMG_W)
                                v = __ldg(ip + gy * IMG_W + gxx);
                            s_in[c][iy][ix] = v;
                        }
                    }
                }
            }
        }
    }
    __syncthreads();

    // ---- Phase 2: horizontal blur ----
    #pragma unroll
    for (int c = 0; c < CH; c++) {
        {
            const float* r = s_in[c][ty];
            s_h[c][ty][tx] = gauss5(r[tx], r[tx+1], r[tx+2], r[tx+3], r[tx+4]);
            if (tx < HB_W - TX) {
                int hx = tx + TX;
                s_h[c][ty][hx] = gauss5(r[hx], r[hx+1], r[hx+2], r[hx+3], r[hx+4]);
            }
        }
        if (ty < IN_H - TY) {
            const float* r = s_in[c][ty + TY];
            s_h[c][ty+TY][tx] = gauss5(r[tx], r[tx+1], r[tx+2], r[tx+3], r[tx+4]);
            if (tx < HB_W - TX) {
                int hx = tx + TX;
                s_h[c][ty+TY][hx] = gauss5(r[hx], r[hx+1], r[hx+2], r[hx+3], r[hx+4]);
            }
        }
    }
    __syncthreads();

    // ---- Phase 3: vertical blur (masked outside image) ----
    #pragma unroll
    for (int c = 0; c < CH; c++) {
        #pragma unroll
        for (int d2 = 0; d2 < 2; d2++) {
            int by = ty + d2 * TY;
            if (by < BL_H) {
                #pragma unroll
                for (int d1 = 0; d1 < 2; d1++) {
                    int hx = tx + d1 * TX;
                    if (hx < HB_W) {
                        float v;
                        if (interior) {
                            v = gauss5(s_h[c][by][hx], s_h[c][by+1][hx], s_h[c][by+2][hx],
                                       s_h[c][by+3][hx], s_h[c][by+4][hx]);
                        } else {
                            int gy = y0 + by - 1, gxx = x0 + hx - 1;
                            v = 0.0f;
                            if ((unsigned)gy < IMG_H && (unsigned)gxx < IMG_W)
                                v = gauss5(s_h[c][by][hx], s_h[c][by+1][hx], s_h[c][by+2][hx],
                                           s_h[c][by+3][hx], s_h[c][by+4][hx]);
                        }
                        s_b[c][by][hx] = v;
                    }
                }
            }
        }
    }
    __syncthreads();

    // ---- Phase 4: Sobel (FROZEN) + mag; hybrid atan2 for bin index ----
    float magAcc = 0.0f, oriApp = 0.0f;
    bool bad = false;
    #pragma unroll
    for (int c = 0; c < CH; c++) {
        float gx, gy;
        sobel_frozen(s_b[c], ty, tx, gx, gy);
        float sq = __fadd_rn(__fmul_rn(gx, gx), __fmul_rn(gy, gy));
        magAcc = __fadd_rn(magAcc, __fsqrt_rn(sq));
        oriApp = oriApp + fast_atan2(gy, gx, bad);
    }

    int y = y0 + ty, x = x0 + tx;
    int o = b * NPIX + y * IMG_W + x;
    g_mag[o] = magAcc;

    // approximate bin; exact recompute only near boundaries (|dq|<=~1e-5 << 1e-3)
    float q = __fdiv_rn(__fadd_rn(__fmul_rn(oriApp, 57.295779513082323f), 180.0f), 45.0f);
    float fr = q - floorf(q);
    if (bad || fabsf(fr - 0.5f) < 1e-3f) {
        // exact R12 chain, gradients recomputed bit-identically from smem
        float s = 0.0f;
        #pragma unroll
        for (int c = 0; c < CH; c++) {
            float gx, gy;
            sobel_frozen(s_b[c], ty, tx, gx, gy);
            s = __fadd_rn(s, atan2f(gy, gx));
        }
        q = __fdiv_rn(__fadd_rn(__fmul_rn(s, 57.295779513082323f), 180.0f), 45.0f);
    }
    int k = (int)rintf(q);              // round half-to-even
    g_idx[o] = (unsigned char)(k & 7);  // Python-style mod 8
}

// ---------------- Kernel 2: NMS with the cross-batch gather quirk ----------
__global__ __launch_bounds__(256) void k2_nms() {
    int b = blockIdx.y;
    int t = blockIdx.x * blockDim.x + threadIdx.x;
    int y = t >> 10;
    int x = t & (IMG_W - 1);

    int base = b * NPIX;
    int d  = (int)g_idx[base + t];
    int dn = (d + 4) & 7;

    int ny = y + c_dy[b];
    int nx = x + c_dx[b];
    bool inb = (ny >= 0) && (ny < IMG_H) && (nx >= 0) && (nx < IMG_W);

    float pos = g_mag[d  * NPIX + t];
    float neg = g_mag[dn * NPIX + t];
    if (inb) {
        int nt = ny * IMG_W + nx;
        pos = __fsub_rn(pos, g_mag[d  * NPIX + nt]);
        neg = __fsub_rn(neg, g_mag[dn * NPIX + nt]);
    }
    float m = g_mag[base + t];
    g_thin[base + t] = (fminf(pos, neg) > 0.0f) ? m : 0.0f;
}

// ---------------- Kernel 3: hysteresis + border zero ----------------------
__global__ __launch_bounds__(256) void k3_hyst(float* __restrict__ out) {
    int b = blockIdx.y;
    int t = blockIdx.x * blockDim.x + threadIdx.x;
    int y = t >> 10;
    int x = t & (IMG_W - 1);

    int base = b * NPIX;
    float e = 0.0f;
    if (y > 0 && y < IMG_H - 1 && x > 0 && x < IMG_W - 1) {
        float tc = g_thin[base + t];
        if (tc > 100.0f) {
            e = 1.0f;
        } else if (tc >= 10.0f) {
            const float* p = g_thin + base + t;
            bool any =
                (p[-IMG_W - 1] > 100.0f) | (p[-IMG_W] > 100.0f) | (p[-IMG_W + 1] > 100.0f) |
                (p[-1]         > 100.0f) |                        (p[1]          > 100.0f) |
                (p[ IMG_W - 1] > 100.0f) | (p[ IMG_W] > 100.0f) | (p[ IMG_W + 1] > 100.0f);
            e = any ? 1.0f : 0.0f;
        }
    }
    out[base + t] = e;
}

// ---------------- Launch ---------------------------------------------------
extern "C" void kernel_launch(void* const* d_in, const int* in_sizes, int n_in,
                              void* d_out, int out_size) {
    const float* img = (const float*)d_in[0];
    float* out = (float*)d_out;

    dim3 blk(TX, TY), grd(IMG_W / TX, IMG_H / TY, BATCH);
    k1_grad<<<grd, blk>>>(img);

    dim3 b2(256), g2(NPIX / 256, BATCH);
    k2_nms<<<g2, b2>>>();
    k3_hyst<<<g2, b2>>>(out);
}

// round 16
// speedup vs baseline: 2.0415x; 1.2145x over previous
#include <cuda_runtime.h>
#include <math.h>

#define IMG_W 1024
#define IMG_H 1024
#define BATCH 8
#define CH    3
#define NPIX  (IMG_H * IMG_W)

// Scratch (static device globals — no allocation allowed)
__device__ float         g_mag[BATCH * NPIX];   // [batch][pixel]
__device__ unsigned char g_idx[BATCH * NPIX];
__device__ float         g_thin[BATCH * NPIX];

__constant__ int c_dy[8] = {0, 1, 1, 1, 0, -1, -1, -1};
__constant__ int c_dx[8] = {1, 1, 0, -1, -1, -1, 0, 1};

// Tile: 64x16 outputs per 512-thread block; 2 adjacent x-pixels per thread.
#define OW 64
#define OH 16
#define IN_W 70
#define IN_H 22
#define IN_WP 72
#define HB_W 66
#define HB_WP 68
#define BL_H 18

// One flat smem buffer; s_b aliases the (dead-after-phase2) s_in region.
#define S_H_OFF (CH * IN_H * IN_WP)                    // 4752 floats
#define SMEM_FLOATS (S_H_OFF + CH * IN_H * HB_WP)      // 9240 floats = 36960 B
#define S_IN(c,iy,ix) smem[(c)*(IN_H*IN_WP) + (iy)*IN_WP + (ix)]
#define S_H(c,r,hx)   smem[S_H_OFF + (c)*(IN_H*HB_WP) + (r)*HB_WP + (hx)]
#define S_B(c,r,hx)   smem[(c)*(BL_H*HB_WP) + (r)*HB_WP + (hx)]

// 5-tap gaussian, NEON-dot pattern (FROZEN NUMERICS — R12 passing variant)
__device__ __forceinline__ float gauss5(float x0, float x1, float x2, float x3, float x4) {
    const float G0 = 0.13533528323661270f;
    const float G1 = 0.60653065971263342f;
    float p0 = __fmul_rn(G0, x0);
    float p1 = __fmul_rn(G1, x1);
    float p2 = x2;
    float p3 = __fmul_rn(G1, x3);
    float p4 = __fmul_rn(G0, x4);
    return __fadd_rn(__fadd_rn(__fadd_rn(p0, p1), __fadd_rn(p2, p3)), p4);
}

// Fast atan2 (R15-validated): octant reduction + Taylor-13, |err|<=~1e-6 rad.
__device__ __forceinline__ float fast_atan2(float y, float x, bool& bad) {
    float ax = fabsf(x), ay = fabsf(y);
    float mn = fminf(ax, ay), mx = fmaxf(ax, ay);
    bad |= !(mn > 0.0f);
    float t = __fdividef(mn, mx);
    bool red = (t > 0.414213562f);
    float u = red ? __fdividef(t - 1.0f, t + 1.0f) : t;
    float u2 = u * u;
    float c = fmaf(u2, 0.0769230769f, -0.0909090909f);
    c = fmaf(u2, c, 0.1111111111f);
    c = fmaf(u2, c, -0.1428571429f);
    c = fmaf(u2, c, 0.2f);
    c = fmaf(u2, c, -0.3333333333f);
    float r = fmaf(u * u2, c, u);
    if (red) r = r + 0.78539816339744831f;
    if (ay > ax) r = 1.57079632679489662f - r;
    if (x < 0.0f) r = 3.14159265358979324f - r;
    return (y < 0.0f) ? -r : r;
}

// FROZEN Sobel association (exact R12 ops) from 8 scalars
__device__ __forceinline__ void sobel9(float a00, float a01, float a02,
                                       float a10, float a12,
                                       float a20, float a21, float a22,
                                       float& gx, float& gy) {
    float gl1 = __fmul_rn(-2.0f, a12);
    float gl2 = __fsub_rn(a20, a02);
    float gl3 = __fmul_rn(2.0f, a10);
    gx = __fadd_rn(__fadd_rn(__fadd_rn(a00, gl1), __fadd_rn(gl2, gl3)),
                   __fmul_rn(-1.0f, a22));
    float hl1 = __fmul_rn(2.0f, a01);
    float hl2 = __fsub_rn(a02, a20);
    float hl3 = __fmul_rn(-2.0f, a21);
    gy = __fadd_rn(__fadd_rn(__fadd_rn(a00, hl1), __fadd_rn(hl2, hl3)),
                   __fmul_rn(-1.0f, a22));
}

// Exact slow-path bin value (libdevice atan2f, FROZEN R12 chain), from smem
__device__ __noinline__ float exact_q(const float* smem, int ty, int col) {
    float s = 0.0f;
    #pragma unroll
    for (int c = 0; c < CH; c++) {
        float a00 = S_B(c,ty  ,col), a01 = S_B(c,ty  ,col+1), a02 = S_B(c,ty  ,col+2);
        float a10 = S_B(c,ty+1,col),                          a12 = S_B(c,ty+1,col+2);
        float a20 = S_B(c,ty+2,col), a21 = S_B(c,ty+2,col+1), a22 = S_B(c,ty+2,col+2);
        float gx, gy;
        sobel9(a00,a01,a02,a10,a12,a20,a21,a22, gx, gy);
        s = __fadd_rn(s, atan2f(gy, gx));
    }
    return __fdiv_rn(__fadd_rn(__fmul_rn(s, 57.295779513082323f), 180.0f), 45.0f);
}

__device__ __forceinline__ void vblur_pair(float* smem, int c, int by, int p,
                                           bool interior, int x0, int y0) {
    float2 v0 = *(const float2*)&S_H(c, by+0, 2*p);
    float2 v1 = *(const float2*)&S_H(c, by+1, 2*p);
    float2 v2 = *(const float2*)&S_H(c, by+2, 2*p);
    float2 v3 = *(const float2*)&S_H(c, by+3, 2*p);
    float2 v4 = *(const float2*)&S_H(c, by+4, 2*p);
    float o0 = gauss5(v0.x, v1.x, v2.x, v3.x, v4.x);
    float o1 = gauss5(v0.y, v1.y, v2.y, v3.y, v4.y);
    if (!interior) {
        int gy = y0 + by - 1;
        int gx0 = x0 + 2*p - 1;
        if (!((unsigned)gy < IMG_H && (unsigned)gx0 < IMG_W))      o0 = 0.0f;
        if (!((unsigned)gy < IMG_H && (unsigned)(gx0+1) < IMG_W))  o1 = 0.0f;
    }
    *(float2*)&S_B(c, by, 2*p) = make_float2(o0, o1);
}

__global__ __launch_bounds__(512) void k1_grad(const float* __restrict__ img) {
    __shared__ __align__(16) float smem[SMEM_FLOATS];

    const int b  = blockIdx.z;
    const int x0 = blockIdx.x * OW;
    const int y0 = blockIdx.y * OH;
    const int tx = threadIdx.x, ty = threadIdx.y;

    const bool interior = (x0 >= 3) & (x0 + IN_W - 3 <= IMG_W) &
                          (y0 >= 3) & (y0 + IN_H - 3 <= IMG_H);

    // ---- Phase 1: load 70x22 x 3ch ----
    #pragma unroll
    for (int c = 0; c < CH; c++) {
        const float* ip = img + (size_t)(b * CH + c) * NPIX;
        #pragma unroll
        for (int k = 0; k < 2; k++) {
            int iy = ty + k * OH;
            if (iy < IN_H) {
                if (interior) {
                    const float* rp = ip + (y0 + iy - 3) * IMG_W + (x0 - 3);
                    S_IN(c, iy, tx)      = __ldg(rp + tx);
                    S_IN(c, iy, tx + 32) = __ldg(rp + tx + 32);
                    if (tx < IN_W - 64) S_IN(c, iy, tx + 64) = __ldg(rp + tx + 64);
                } else {
                    int gy = y0 + iy - 3;
                    #pragma unroll
                    for (int d = 0; d < 3; d++) {
                        int ix = tx + d * 32;
                        if (ix < IN_W) {
                            int gx = x0 + ix - 3;
                            float v = 0.0f;
                            if ((unsigned)gy < IMG_H && (unsigned)gx < IMG_W)
                                v = __ldg(ip + gy * IMG_W + gx);
                            S_IN(c, iy, ix) = v;
                        }
                    }
                }
            }
        }
    }
    __syncthreads();

    // ---- Phase 2: horizontal blur, 33 float2-pairs x 22 rows per channel ----
    #pragma unroll
    for (int c = 0; c < CH; c++) {
        #pragma unroll
        for (int k = 0; k < 2; k++) {
            int row = ty + k * OH;
            if (row < IN_H) {
                const float2* r2 = (const float2*)&S_IN(c, row, 0);
                float2* o2 = (float2*)&S_H(c, row, 0);
                {
                    float2 A = r2[tx], B = r2[tx+1], C = r2[tx+2];
                    o2[tx] = make_float2(gauss5(A.x, A.y, B.x, B.y, C.x),
                                         gauss5(A.y, B.x, B.y, C.x, C.y));
                }
                if (tx == 0) {
                    float2 A = r2[32], B = r2[33], C = r2[34];
                    o2[32] = make_float2(gauss5(A.x, A.y, B.x, B.y, C.x),
                                         gauss5(A.y, B.x, B.y, C.x, C.y));
                }
            }
        }
    }
    __syncthreads();

    // ---- Phase 3: vertical blur into s_b (aliases dead s_in) ----
    #pragma unroll
    for (int c = 0; c < CH; c++) {
        #pragma unroll
        for (int k = 0; k < 2; k++) {
            int by = ty + k * OH;
            if (by < BL_H) {
                vblur_pair(smem, c, by, tx, interior, x0, y0);
                if (tx == 0) vblur_pair(smem, c, by, 32, interior, x0, y0);
            }
        }
    }
    __syncthreads();

    // ---- Phase 4: Sobel (FROZEN) + mag + hybrid atan2, 2 pixels/thread ----
    float mag0 = 0.0f, mag1 = 0.0f, ori0 = 0.0f, ori1 = 0.0f;
    bool bad0 = false, bad1 = false;
    #pragma unroll
    for (int c = 0; c < CH; c++) {
        float2 e0 = *(const float2*)&S_B(c, ty+0, 2*tx);
        float2 f0 = *(const float2*)&S_B(c, ty+0, 2*tx+2);
        float2 e1 = *(const float2*)&S_B(c, ty+1, 2*tx);
        float2 f1 = *(const float2*)&S_B(c, ty+1, 2*tx+2);
        float2 e2 = *(const float2*)&S_B(c, ty+2, 2*tx);
        float2 f2 = *(const float2*)&S_B(c, ty+2, 2*tx+2);

        float gx, gy;
        // pixel 0: cols (e.x, e.y, f.x)
        sobel9(e0.x, e0.y, f0.x, e1.x, f1.x, e2.x, e2.y, f2.x, gx, gy);
        float sq = __fadd_rn(__fmul_rn(gx, gx), __fmul_rn(gy, gy));
        mag0 = __fadd_rn(mag0, __fsqrt_rn(sq));
        ori0 = ori0 + fast_atan2(gy, gx, bad0);
        // pixel 1: cols (e.y, f.x, f.y)
        sobel9(e0.y, f0.x, f0.y, e1.y, f1.y, e2.y, f2.x, f2.y, gx, gy);
        sq = __fadd_rn(__fmul_rn(gx, gx), __fmul_rn(gy, gy));
        mag1 = __fadd_rn(mag1, __fsqrt_rn(sq));
        ori1 = ori1 + fast_atan2(gy, gx, bad1);
    }

    int y = y0 + ty, x = x0 + 2 * tx;
    int o = b * NPIX + y * IMG_W + x;
    *(float2*)&g_mag[o] = make_float2(mag0, mag1);

    float q0 = __fdiv_rn(__fadd_rn(__fmul_rn(ori0, 57.295779513082323f), 180.0f), 45.0f);
    float fr0 = q0 - floorf(q0);
    if (bad0 || fabsf(fr0 - 0.5f) < 1e-3f) q0 = exact_q(smem, ty, 2*tx);
    float q1 = __fdiv_rn(__fadd_rn(__fmul_rn(ori1, 57.295779513082323f), 180.0f), 45.0f);
    float fr1 = q1 - floorf(q1);
    if (bad1 || fabsf(fr1 - 0.5f) < 1e-3f) q1 = exact_q(smem, ty, 2*tx + 1);

    unsigned char k0 = (unsigned char)(((int)rintf(q0)) & 7);
    unsigned char k1v = (unsigned char)(((int)rintf(q1)) & 7);
    *(uchar2*)&g_idx[o] = make_uchar2(k0, k1v);
}

// ---------------- Kernel 2: NMS with the cross-batch gather quirk ----------
__global__ __launch_bounds__(256) void k2_nms() {
    int b = blockIdx.y;
    int t = blockIdx.x * blockDim.x + threadIdx.x;
    int y = t >> 10;
    int x = t & (IMG_W - 1);

    int base = b * NPIX;
    int d  = (int)g_idx[base + t];
    int dn = (d + 4) & 7;

    int ny = y + c_dy[b];
    int nx = x + c_dx[b];
    bool inb = (ny >= 0) && (ny < IMG_H) && (nx >= 0) && (nx < IMG_W);

    float pos = g_mag[d  * NPIX + t];
    float neg = g_mag[dn * NPIX + t];
    if (inb) {
        int nt = ny * IMG_W + nx;
        pos = __fsub_rn(pos, g_mag[d  * NPIX + nt]);
        neg = __fsub_rn(neg, g_mag[dn * NPIX + nt]);
    }
    float m = g_mag[base + t];
    g_thin[base + t] = (fminf(pos, neg) > 0.0f) ? m : 0.0f;
}

// ---------------- Kernel 3: hysteresis + border zero ----------------------
__global__ __launch_bounds__(256) void k3_hyst(float* __restrict__ out) {
    int b = blockIdx.y;
    int t = blockIdx.x * blockDim.x + threadIdx.x;
    int y = t >> 10;
    int x = t & (IMG_W - 1);

    int base = b * NPIX;
    float e = 0.0f;
    if (y > 0 && y < IMG_H - 1 && x > 0 && x < IMG_W - 1) {
        float tc = g_thin[base + t];
        if (tc > 100.0f) {
            e = 1.0f;
        } else if (tc >= 10.0f) {
            const float* p = g_thin + base + t;
            bool any =
                (p[-IMG_W - 1] > 100.0f) | (p[-IMG_W] > 100.0f) | (p[-IMG_W + 1] > 100.0f) |
                (p[-1]         > 100.0f) |                        (p[1]          > 100.0f) |
                (p[ IMG_W - 1] > 100.0f) | (p[ IMG_W] > 100.0f) | (p[ IMG_W + 1] > 100.0f);
            e = any ? 1.0f : 0.0f;
        }
    }
    out[base + t] = e;
}

// ---------------- Launch ---------------------------------------------------
extern "C" void kernel_launch(void* const* d_in, const int* in_sizes, int n_in,
                              void* d_out, int out_size) {
    const float* img = (const float*)d_in[0];
    float* out = (float*)d_out;

    dim3 blk(32, 16), grd(IMG_W / OW, IMG_H / OH, BATCH);
    k1_grad<<<grd, blk>>>(img);

    dim3 b2(256), g2(NPIX / 256, BATCH);
    k2_nms<<<g2, b2>>>();
    k3_hyst<<<g2, b2>>>(out);
}

// round 17
// speedup vs baseline: 2.1667x; 1.0614x over previous
#include <cuda_runtime.h>
#include <math.h>

#define IMG_W 1024
#define IMG_H 1024
#define BATCH 8
#define CH    3
#define NPIX  (IMG_H * IMG_W)

// Scratch (static device globals — no allocation allowed)
__device__ float         g_mag[BATCH * NPIX];   // [batch][pixel]
__device__ unsigned char g_idx[BATCH * NPIX];
__device__ unsigned char g_cls[BATCH * NPIX];   // 0=weak, 1=middle, 2=strong

__constant__ int c_dy[8] = {0, 1, 1, 1, 0, -1, -1, -1};
__constant__ int c_dx[8] = {1, 1, 0, -1, -1, -1, 0, 1};

// Tile: 64x16 outputs per 512-thread block; 2 adjacent x-pixels per thread.
#define OW 64
#define OH 16
#define IN_W 70
#define IN_H 22
#define IN_WP 72
#define HB_W 66
#define HB_WP 68
#define BL_H 18

#define S_H_OFF (CH * IN_H * IN_WP)
#define SMEM_FLOATS (S_H_OFF + CH * IN_H * HB_WP)
#define S_IN(c,iy,ix) smem[(c)*(IN_H*IN_WP) + (iy)*IN_WP + (ix)]
#define S_H(c,r,hx)   smem[S_H_OFF + (c)*(IN_H*HB_WP) + (r)*HB_WP + (hx)]
#define S_B(c,r,hx)   smem[(c)*(BL_H*HB_WP) + (r)*HB_WP + (hx)]

// 5-tap gaussian, NEON-dot pattern (FROZEN NUMERICS — R12 passing variant)
__device__ __forceinline__ float gauss5(float x0, float x1, float x2, float x3, float x4) {
    const float G0 = 0.13533528323661270f;
    const float G1 = 0.60653065971263342f;
    float p0 = __fmul_rn(G0, x0);
    float p1 = __fmul_rn(G1, x1);
    float p2 = x2;
    float p3 = __fmul_rn(G1, x3);
    float p4 = __fmul_rn(G0, x4);
    return __fadd_rn(__fadd_rn(__fadd_rn(p0, p1), __fadd_rn(p2, p3)), p4);
}

// Fast atan2: |y/x| folded to [0,1], A&S 4.4.49 minimax deg-9 (|err|<=1e-5 rad).
// Bin error <= 3.8e-5 << 1e-3 gate. Zero/NaN operands flag 'bad' -> exact path.
__device__ __forceinline__ float fast_atan2(float y, float x, bool& bad) {
    float ax = fabsf(x), ay = fabsf(y);
    float mn = fminf(ax, ay), mx = fmaxf(ax, ay);
    bad |= !(mn > 0.0f);
    float t = __fdividef(mn, mx);
    float t2 = t * t;
    float p = fmaf(t2, 0.0208351f, -0.0851330f);
    p = fmaf(t2, p, 0.1801410f);
    p = fmaf(t2, p, -0.3302995f);
    p = fmaf(t2, p, 0.9998660f);
    float r = t * p;
    if (ay > ax) r = 1.57079632679489662f - r;
    if (x < 0.0f) r = 3.14159265358979324f - r;
    return (y < 0.0f) ? -r : r;
}

// FROZEN Sobel association (exact R12 ops)
__device__ __forceinline__ void sobel9(float a00, float a01, float a02,
                                       float a10, float a12,
                                       float a20, float a21, float a22,
                                       float& gx, float& gy) {
    float gl1 = __fmul_rn(-2.0f, a12);
    float gl2 = __fsub_rn(a20, a02);
    float gl3 = __fmul_rn(2.0f, a10);
    gx = __fadd_rn(__fadd_rn(__fadd_rn(a00, gl1), __fadd_rn(gl2, gl3)),
                   __fmul_rn(-1.0f, a22));
    float hl1 = __fmul_rn(2.0f, a01);
    float hl2 = __fsub_rn(a02, a20);
    float hl3 = __fmul_rn(-2.0f, a21);
    gy = __fadd_rn(__fadd_rn(__fadd_rn(a00, hl1), __fadd_rn(hl2, hl3)),
                   __fmul_rn(-1.0f, a22));
}

// Exact slow-path bin value (libdevice atan2f, FROZEN R12 chain)
__device__ __noinline__ float exact_q(const float* smem, int ty, int col) {
    float s = 0.0f;
    #pragma unroll
    for (int c = 0; c < CH; c++) {
        float a00 = S_B(c,ty  ,col), a01 = S_B(c,ty  ,col+1), a02 = S_B(c,ty  ,col+2);
        float a10 = S_B(c,ty+1,col),                          a12 = S_B(c,ty+1,col+2);
        float a20 = S_B(c,ty+2,col), a21 = S_B(c,ty+2,col+1), a22 = S_B(c,ty+2,col+2);
        float gx, gy;
        sobel9(a00,a01,a02,a10,a12,a20,a21,a22, gx, gy);
        s = __fadd_rn(s, atan2f(gy, gx));
    }
    return __fdiv_rn(__fadd_rn(__fmul_rn(s, 57.295779513082323f), 180.0f), 45.0f);
}

__device__ __forceinline__ void vblur_pair(float* smem, int c, int by, int p,
                                           bool interior, int x0, int y0) {
    float2 v0 = *(const float2*)&S_H(c, by+0, 2*p);
    float2 v1 = *(const float2*)&S_H(c, by+1, 2*p);
    float2 v2 = *(const float2*)&S_H(c, by+2, 2*p);
    float2 v3 = *(const float2*)&S_H(c, by+3, 2*p);
    float2 v4 = *(const float2*)&S_H(c, by+4, 2*p);
    float o0 = gauss5(v0.x, v1.x, v2.x, v3.x, v4.x);
    float o1 = gauss5(v0.y, v1.y, v2.y, v3.y, v4.y);
    if (!interior) {
        int gy = y0 + by - 1;
        int gx0 = x0 + 2*p - 1;
        if (!((unsigned)gy < IMG_H && (unsigned)gx0 < IMG_W))      o0 = 0.0f;
        if (!((unsigned)gy < IMG_H && (unsigned)(gx0+1) < IMG_W))  o1 = 0.0f;
    }
    *(float2*)&S_B(c, by, 2*p) = make_float2(o0, o1);
}

__global__ __launch_bounds__(512) void k1_grad(const float* __restrict__ img) {
    __shared__ __align__(16) float smem[SMEM_FLOATS];

    const int b  = blockIdx.z;
    const int x0 = blockIdx.x * OW;
    const int y0 = blockIdx.y * OH;
    const int tx = threadIdx.x, ty = threadIdx.y;

    const bool interior = (x0 >= 3) & (x0 + IN_W - 3 <= IMG_W) &
                          (y0 >= 3) & (y0 + IN_H - 3 <= IMG_H);

    // ---- Phase 1: load 70x22 x 3ch ----
    #pragma unroll
    for (int c = 0; c < CH; c++) {
        const float* ip = img + (size_t)(b * CH + c) * NPIX;
        #pragma unroll
        for (int k = 0; k < 2; k++) {
            int iy = ty + k * OH;
            if (iy < IN_H) {
                if (interior) {
                    const float* rp = ip + (y0 + iy - 3) * IMG_W + (x0 - 3);
                    S_IN(c, iy, tx)      = __ldg(rp + tx);
                    S_IN(c, iy, tx + 32) = __ldg(rp + tx + 32);
                    if (tx < IN_W - 64) S_IN(c, iy, tx + 64) = __ldg(rp + tx + 64);
                } else {
                    int gy = y0 + iy - 3;
                    #pragma unroll
                    for (int d = 0; d < 3; d++) {
                        int ix = tx + d * 32;
                        if (ix < IN_W) {
                            int gx = x0 + ix - 3;
                            float v = 0.0f;
                            if ((unsigned)gy < IMG_H && (unsigned)gx < IMG_W)
                                v = __ldg(ip + gy * IMG_W + gx);
                            S_IN(c, iy, ix) = v;
                        }
                    }
                }
            }
        }
    }
    __syncthreads();

    // ---- Phase 2: horizontal blur (float2 pairs) ----
    #pragma unroll
    for (int c = 0; c < CH; c++) {
        #pragma unroll
        for (int k = 0; k < 2; k++) {
            int row = ty + k * OH;
            if (row < IN_H) {
                const float2* r2 = (const float2*)&S_IN(c, row, 0);
                float2* o2 = (float2*)&S_H(c, row, 0);
                {
                    float2 A = r2[tx], B = r2[tx+1], C = r2[tx+2];
                    o2[tx] = make_float2(gauss5(A.x, A.y, B.x, B.y, C.x),
                                         gauss5(A.y, B.x, B.y, C.x, C.y));
                }
                if (tx == 0) {
                    float2 A = r2[32], B = r2[33], C = r2[34];
                    o2[32] = make_float2(gauss5(A.x, A.y, B.x, B.y, C.x),
                                         gauss5(A.y, B.x, B.y, C.x, C.y));
                }
            }
        }
    }
    __syncthreads();

    // ---- Phase 3: vertical blur into s_b (aliases dead s_in) ----
    #pragma unroll
    for (int c = 0; c < CH; c++) {
        #pragma unroll
        for (int k = 0; k < 2; k++) {
            int by = ty + k * OH;
            if (by < BL_H) {
                vblur_pair(smem, c, by, tx, interior, x0, y0);
                if (tx == 0) vblur_pair(smem, c, by, 32, interior, x0, y0);
            }
        }
    }
    __syncthreads();

    // ---- Phase 4: Sobel (FROZEN) + mag + hybrid atan2, 2 pixels/thread ----
    float mag0 = 0.0f, mag1 = 0.0f, ori0 = 0.0f, ori1 = 0.0f;
    bool bad0 = false, bad1 = false;
    #pragma unroll
    for (int c = 0; c < CH; c++) {
        float2 e0 = *(const float2*)&S_B(c, ty+0, 2*tx);
        float2 f0 = *(const float2*)&S_B(c, ty+0, 2*tx+2);
        float2 e1 = *(const float2*)&S_B(c, ty+1, 2*tx);
        float2 f1 = *(const float2*)&S_B(c, ty+1, 2*tx+2);
        float2 e2 = *(const float2*)&S_B(c, ty+2, 2*tx);
        float2 f2 = *(const float2*)&S_B(c, ty+2, 2*tx+2);

        float gx, gy;
        sobel9(e0.x, e0.y, f0.x, e1.x, f1.x, e2.x, e2.y, f2.x, gx, gy);
        float sq = __fadd_rn(__fmul_rn(gx, gx), __fmul_rn(gy, gy));
        mag0 = __fadd_rn(mag0, __fsqrt_rn(sq));
        ori0 = ori0 + fast_atan2(gy, gx, bad0);

        sobel9(e0.y, f0.x, f0.y, e1.y, f1.y, e2.y, f2.x, f2.y, gx, gy);
        sq = __fadd_rn(__fmul_rn(gx, gx), __fmul_rn(gy, gy));
        mag1 = __fadd_rn(mag1, __fsqrt_rn(sq));
        ori1 = ori1 + fast_atan2(gy, gx, bad1);
    }

    int y = y0 + ty, x = x0 + 2 * tx;
    int o = b * NPIX + y * IMG_W + x;
    *(float2*)&g_mag[o] = make_float2(mag0, mag1);

    float q0 = __fdiv_rn(__fadd_rn(__fmul_rn(ori0, 57.295779513082323f), 180.0f), 45.0f);
    float fr0 = q0 - floorf(q0);
    if (bad0 || fabsf(fr0 - 0.5f) < 1e-3f) q0 = exact_q(smem, ty, 2*tx);
    float q1 = __fdiv_rn(__fadd_rn(__fmul_rn(ori1, 57.295779513082323f), 180.0f), 45.0f);
    float fr1 = q1 - floorf(q1);
    if (bad1 || fabsf(fr1 - 0.5f) < 1e-3f) q1 = exact_q(smem, ty, 2*tx + 1);

    unsigned char k0 = (unsigned char)(((int)rintf(q0)) & 7);
    unsigned char k1v = (unsigned char)(((int)rintf(q1)) & 7);
    *(uchar2*)&g_idx[o] = make_uchar2(k0, k1v);
}

// -------- Kernel 2: NMS (cross-batch gather) -> 2-bit class, 4 px/thread ----
__global__ __launch_bounds__(256) void k2_nms() {
    int b = blockIdx.y;
    int t = (blockIdx.x * 256 + threadIdx.x) * 4;
    int base = b * NPIX;
    int y = t >> 10;
    int x = t & (IMG_W - 1);

    uchar4 d4 = *(const uchar4*)&g_idx[base + t];
    float4 m4 = *(const float4*)&g_mag[base + t];

    int ddy = c_dy[b], ddx = c_dx[b];
    int noff = ddy * IMG_W + ddx;
    bool yok = (unsigned)(y + ddy) < IMG_H;

    unsigned char dd[4] = {d4.x, d4.y, d4.z, d4.w};
    const float* mm = &m4.x;
    unsigned char cls[4];
    #pragma unroll
    for (int i = 0; i < 4; i++) {
        int d  = (int)dd[i];
        int dn = (d + 4) & 7;
        float pos = __ldg(&g_mag[d  * NPIX + t + i]);
        float neg = __ldg(&g_mag[dn * NPIX + t + i]);
        int nx = x + i + ddx;
        if (yok && (unsigned)nx < IMG_W) {
            pos = __fsub_rn(pos, __ldg(&g_mag[d  * NPIX + t + i + noff]));
            neg = __fsub_rn(neg, __ldg(&g_mag[dn * NPIX + t + i + noff]));
        }
        unsigned char cv = 0;
        if (fminf(pos, neg) > 0.0f) {
            float m = mm[i];
            cv = (m > 100.0f) ? 2 : ((m >= 10.0f) ? 1 : 0);
        }
        cls[i] = cv;
    }
    *(uchar4*)&g_cls[base + t] = make_uchar4(cls[0], cls[1], cls[2], cls[3]);
}

// ------------- Kernel 3: hysteresis on classes + border zero ---------------
__global__ __launch_bounds__(256) void k3_hyst(float* __restrict__ out) {
    int b = blockIdx.y;
    int t = (blockIdx.x * 256 + threadIdx.x) * 4;
    int base = b * NPIX;
    int y = t >> 10;
    int xq = t & (IMG_W - 1);

    float4 e = make_float4(0.0f, 0.0f, 0.0f, 0.0f);
    if (y > 0 && y < IMG_H - 1) {
        const unsigned char* pc = g_cls + base + t;
        uchar4 cm = *(const uchar4*)pc;
        uchar4 cu = *(const uchar4*)(pc - IMG_W);
        uchar4 cd = *(const uchar4*)(pc + IMG_W);
        unsigned lu = 0, lm = 0, ld = 0, ru = 0, rm = 0, rd = 0;
        if (xq > 0)           { lu = pc[-IMG_W - 1]; lm = pc[-1]; ld = pc[IMG_W - 1]; }
        if (xq < IMG_W - 4)   { ru = pc[-IMG_W + 4]; rm = pc[4];  rd = pc[IMG_W + 4]; }
        unsigned up[6] = {lu, cu.x, cu.y, cu.z, cu.w, ru};
        unsigned mi[6] = {lm, cm.x, cm.y, cm.z, cm.w, rm};
        unsigned dn[6] = {ld, cd.x, cd.y, cd.z, cd.w, rd};
        float* ep = &e.x;
        #pragma unroll
        for (int i = 0; i < 4; i++) {
            unsigned cen = mi[i + 1];
            unsigned any = (up[i] | up[i+1] | up[i+2] | mi[i] | mi[i+2] |
                            dn[i] | dn[i+1] | dn[i+2]) & 2u;
            float v = (cen == 2u || (cen == 1u && any)) ? 1.0f : 0.0f;
            int xx = xq + i;
            if (xx == 0 || xx == IMG_W - 1) v = 0.0f;
            ep[i] = v;
        }
    }
    *(float4*)&out[base + t] = e;
}

// ---------------- Launch ---------------------------------------------------
extern "C" void kernel_launch(void* const* d_in, const int* in_sizes, int n_in,
                              void* d_out, int out_size) {
    const float* img = (const float*)d_in[0];
    float* out = (float*)d_out;

    dim3 blk(32, 16), grd(IMG_W / OW, IMG_H / OH, BATCH);
    k1_grad<<<grd, blk>>>(img);

    dim3 b2(256), g2(NPIX / 1024, BATCH);
    k2_nms<<<g2, b2>>>();
    k3_hyst<<<g2, b2>>>(out);
}